// round 1
// baseline (speedup 1.0000x reference)
#include <cuda_runtime.h>

// Problem constants (fixed for this problem instance)
#define CFRAME 384
#define NAA    21
#define PAD    25          // odd stride -> conflict-free SMEM weight reads
#define NRES   2048
#define NRIG   8192
#define BATCH  16
#define WARPS_PER_BLOCK 8
#define THREADS (WARPS_PER_BLOCK * 32)
#define NBLOCKS 444        // 3 blocks/SM on 148 SMs
#define SMEM_FLOATS (CFRAME * PAD + WARPS_PER_BLOCK * 32 * PAD)
#define SMEM_BYTES  (SMEM_FLOATS * 4)

// Scratch (no allocations allowed): combined weight Wc = W_su @ W_out, padded [384][25]
__device__ float g_Wc[CFRAME * PAD];
__device__ float g_bsuc[NAA];   // b_su @ W_out
__device__ int   g_idx64;       // 1 if rigids_to_res_idx is int64, 0 if int32

// ---------------------------------------------------------------------------
// Kernel A: fold W_su @ W_out -> g_Wc (padded), b_su @ W_out -> g_bsuc
// ---------------------------------------------------------------------------
__global__ void prep_kernel(const float* __restrict__ W_su,
                            const float* __restrict__ b_su,
                            const float* __restrict__ W_out) {
    int idx = blockIdx.x * blockDim.x + threadIdx.x;
    const int total = CFRAME * PAD;
    if (idx < total) {
        int c = idx / PAD;
        int a = idx - c * PAD;
        float acc = 0.f;
        if (a < NAA) {
            const float* wr = W_su + (size_t)c * CFRAME;
            for (int s = 0; s < CFRAME; s++)
                acc = fmaf(wr[s], W_out[s * NAA + a], acc);
        }
        g_Wc[idx] = acc;
    } else if (idx < total + NAA) {
        int a = idx - total;
        float acc = 0.f;
        for (int s = 0; s < CFRAME; s++)
            acc = fmaf(b_su[s], W_out[s * NAA + a], acc);
        g_bsuc[a] = acc;
    }
}

// ---------------------------------------------------------------------------
// Detect index dtype at runtime (JAX int64 request may canonicalize to int32).
// If buffer really is int64, every value is in [0, NRES). If it's int32 pairs,
// the int64 view mixes two random indices -> huge values almost surely.
// ---------------------------------------------------------------------------
__global__ void detect_idx_kernel(const void* __restrict__ idx_ptr) {
    if (threadIdx.x == 0 && blockIdx.x == 0) {
        const long long* p = (const long long*)idx_ptr;
        int is64 = 1;
        for (int i = 0; i < 64; i++) {
            long long v = p[i];
            if (v < 0 || v >= NRES) { is64 = 0; break; }
        }
        g_idx64 = is64;
    }
}

// ---------------------------------------------------------------------------
// Kernel B: d_out[b,r,:] = out[b,r,:] @ W_out + b_out   (initializes d_out)
// Warp-per-row; W_out staged in SMEM padded to stride 25; swizzled-stage reduce.
// ---------------------------------------------------------------------------
__global__ void __launch_bounds__(THREADS)
res_proj_kernel(const float* __restrict__ seq_out,   // [B*NRES, 384]
                const float* __restrict__ W_out,     // [384, 21]
                const float* __restrict__ b_out,     // [21]
                float* __restrict__ out) {           // [B*NRES, 21]
    extern __shared__ float smem[];
    float* Ws    = smem;                  // CFRAME*PAD
    float* stage = smem + CFRAME * PAD;   // WARPS*32*PAD

    for (int i = threadIdx.x; i < CFRAME * PAD; i += THREADS) {
        int c = i / PAD;
        int a = i - c * PAD;
        Ws[i] = (a < NAA) ? W_out[c * NAA + a] : 0.f;
    }
    __syncthreads();

    const int lane = threadIdx.x & 31;
    const int w    = threadIdx.x >> 5;
    float* st = stage + w * 32 * PAD;
    const int warpsTotal = gridDim.x * WARPS_PER_BLOCK;
    const int gw = blockIdx.x * WARPS_PER_BLOCK + w;
    const int nrows = BATCH * NRES;
    const float bo = (lane < NAA) ? b_out[lane] : 0.f;

    for (int row = gw; row < nrows; row += warpsTotal) {
        const float* xr = seq_out + (size_t)row * CFRAME;
        float xv[12];
#pragma unroll
        for (int k = 0; k < 12; k++) xv[k] = xr[lane + 32 * k];

        float acc[NAA];
#pragma unroll
        for (int a = 0; a < NAA; a++) acc[a] = 0.f;
#pragma unroll
        for (int k = 0; k < 12; k++) {
            const float* wr = Ws + (lane + 32 * k) * PAD;
            float xk = xv[k];
#pragma unroll
            for (int a = 0; a < NAA; a++) acc[a] = fmaf(xk, wr[a], acc[a]);
        }
        // swizzled stage: store (lane, (a+lane)%25); conflict-free both phases
#pragma unroll
        for (int a = 0; a < NAA; a++) {
            int col = a + lane;
            if (col >= PAD) col -= PAD;
            if (col >= PAD) col -= PAD;
            st[lane * PAD + col] = acc[a];
        }
        __syncwarp();
        if (lane < NAA) {
            float red = 0.f;
            int col = lane;
#pragma unroll
            for (int l = 0; l < 32; l++) {
                red += st[l * PAD + col];
                col++; if (col == PAD) col = 0;
            }
            out[(size_t)row * NAA + lane] = red + bo;
        }
        __syncwarp();
    }
}

// ---------------------------------------------------------------------------
// Kernel C: per rigid row: LayerNorm -> @ Wc (+ bsuc), * mask, atomic scatter
// into d_out[b, idx[row], :21]. Warp-per-row, persistent blocks.
// ---------------------------------------------------------------------------
__global__ void __launch_bounds__(THREADS)
rigid_kernel(const float* __restrict__ x,        // [B*NRIG, 384]
             const void*  __restrict__ idx_ptr,  // [B*NRIG] int32 or int64
             const float* __restrict__ mask,     // [B*NRIG]
             const float* __restrict__ ln_g,
             const float* __restrict__ ln_b,
             float* __restrict__ out) {          // [B*NRES, 21]
    extern __shared__ float smem[];
    float* Ws    = smem;
    float* stage = smem + CFRAME * PAD;

    for (int i = threadIdx.x; i < CFRAME * PAD; i += THREADS) Ws[i] = g_Wc[i];
    __syncthreads();

    const int lane = threadIdx.x & 31;
    const int w    = threadIdx.x >> 5;
    float* st = stage + w * 32 * PAD;

    float gg[12], bb[12];
#pragma unroll
    for (int k = 0; k < 12; k++) {
        gg[k] = ln_g[lane + 32 * k];
        bb[k] = ln_b[lane + 32 * k];
    }
    const long long* idx64 = (const long long*)idx_ptr;
    const int*       idx32 = (const int*)idx_ptr;
    const int use64 = g_idx64;
    const float bs = (lane < NAA) ? g_bsuc[lane] : 0.f;

    const int warpsTotal = gridDim.x * WARPS_PER_BLOCK;
    const int gw = blockIdx.x * WARPS_PER_BLOCK + w;
    const int nrows = BATCH * NRIG;

    for (int row = gw; row < nrows; row += warpsTotal) {
        const float* xr = x + (size_t)row * CFRAME;
        float xv[12];
#pragma unroll
        for (int k = 0; k < 12; k++) xv[k] = xr[lane + 32 * k];

        // LayerNorm statistics
        float s = 0.f, s2 = 0.f;
#pragma unroll
        for (int k = 0; k < 12; k++) { s += xv[k]; s2 = fmaf(xv[k], xv[k], s2); }
#pragma unroll
        for (int o = 16; o; o >>= 1) {
            s  += __shfl_xor_sync(0xffffffffu, s,  o);
            s2 += __shfl_xor_sync(0xffffffffu, s2, o);
        }
        const float mu   = s * (1.f / CFRAME);
        const float var  = fmaf(s2, 1.f / CFRAME, -mu * mu);
        const float rstd = rsqrtf(var + 1e-5f);
#pragma unroll
        for (int k = 0; k < 12; k++)
            xv[k] = fmaf((xv[k] - mu) * rstd, gg[k], bb[k]);

        // xn @ Wc  (lane owns channels c = lane + 32k; Ws stride 25 -> no conflicts)
        float acc[NAA];
#pragma unroll
        for (int a = 0; a < NAA; a++) acc[a] = 0.f;
#pragma unroll
        for (int k = 0; k < 12; k++) {
            const float* wr = Ws + (lane + 32 * k) * PAD;
            float xk = xv[k];
#pragma unroll
            for (int a = 0; a < NAA; a++) acc[a] = fmaf(xk, wr[a], acc[a]);
        }

        // cross-lane reduce via swizzled SMEM stage
#pragma unroll
        for (int a = 0; a < NAA; a++) {
            int col = a + lane;
            if (col >= PAD) col -= PAD;
            if (col >= PAD) col -= PAD;
            st[lane * PAD + col] = acc[a];
        }
        __syncwarp();

        const float m = mask[row];
        const int resid = use64 ? (int)idx64[row] : idx32[row];
        if (lane < NAA && m != 0.f) {
            float red = 0.f;
            int col = lane;
#pragma unroll
            for (int l = 0; l < 32; l++) {
                red += st[l * PAD + col];
                col++; if (col == PAD) col = 0;
            }
            const int b = row / NRIG;
            float* dst = out + ((size_t)b * NRES + resid) * NAA;
            atomicAdd(dst + lane, (red + bs) * m);
        }
        __syncwarp();
    }
}

// ---------------------------------------------------------------------------
// Launch
// ---------------------------------------------------------------------------
extern "C" void kernel_launch(void* const* d_in, const int* in_sizes, int n_in,
                              void* d_out, int out_size) {
    const float* x     = (const float*)d_in[0];  // rigids_embed_flat [16,8192,384]
    const void*  idxp  = d_in[1];                // rigids_to_res_idx [16,8192]
    const float* mask  = (const float*)d_in[2];  // rigids_mask [16,8192]
    const float* seqo  = (const float*)d_in[3];  // out [16,2048,384]
    const float* ln_g  = (const float*)d_in[4];
    const float* ln_b  = (const float*)d_in[5];
    const float* W_su  = (const float*)d_in[6];  // [384,384]
    const float* b_su  = (const float*)d_in[7];  // [384]
    const float* W_out = (const float*)d_in[8];  // [384,21]
    const float* b_out = (const float*)d_in[9];  // [21]
    float* out = (float*)d_out;                  // [16,2048,21]

    cudaFuncSetAttribute(res_proj_kernel,
                         cudaFuncAttributeMaxDynamicSharedMemorySize, SMEM_BYTES);
    cudaFuncSetAttribute(rigid_kernel,
                         cudaFuncAttributeMaxDynamicSharedMemorySize, SMEM_BYTES);

    const int prep_threads = CFRAME * PAD + NAA;
    prep_kernel<<<(prep_threads + 255) / 256, 256>>>(W_su, b_su, W_out);
    detect_idx_kernel<<<1, 32>>>(idxp);
    res_proj_kernel<<<NBLOCKS, THREADS, SMEM_BYTES>>>(seqo, W_out, b_out, out);
    rigid_kernel<<<NBLOCKS, THREADS, SMEM_BYTES>>>(x, idxp, mask, ln_g, ln_b, out);
}

// round 2
// speedup vs baseline: 1.2759x; 1.2759x over previous
#include <cuda_runtime.h>

#define CFRAME 384
#define KITER  12
#define NAA    21
#define NPAIR  11          // a-pairs; pair10 = (a20, ones-column)
#define NRES   2048
#define NRIG   8192
#define BATCH  16
#define WARPS  8
#define THREADS 256
#define NBLOCKS 296        // 2 persistent blocks / SM
#define STRIDE 25          // stage stride in float2 (odd -> conflict-free)
#define WSZ (CFRAME*NPAIR)           // weight float2 count
#define STAGESZ (WARPS*32*STRIDE)    // stage float2 count
#define SMEM_BYTES ((WSZ+STAGESZ)*8)

typedef unsigned long long u64;

// device scratch (no allocations allowed)
__device__ float2 g_Wg2[WSZ];   // ln_g-folded (W_su@W_out) as a-pairs; pair10.y = 1 (ones col)
__device__ float2 g_Wo2[WSZ];   // W_out as a-pairs; pair10.y = 0
__device__ float2 g_A2[NPAIR];  // A = sum_c g*Wc
__device__ float2 g_B2[NPAIR];  // B = sum_c b*Wc + b_su@W_out
__device__ float2 g_Bo2[NPAIR]; // b_out pairs
__device__ float  g_Wc[CFRAME*NAA];
__device__ int    g_idx64;

// ---- packed f32x2 helpers ----
__device__ __forceinline__ u64 pk2(float lo, float hi){u64 r;asm("mov.b64 %0,{%1,%2};":"=l"(r):"f"(lo),"f"(hi));return r;}
__device__ __forceinline__ u64 dup2(float v){return pk2(v,v);}
__device__ __forceinline__ void upk2(u64 v,float&lo,float&hi){asm("mov.b64 {%0,%1},%2;":"=f"(lo),"=f"(hi):"l"(v));}
__device__ __forceinline__ u64 fma2(u64 a,u64 b,u64 c){u64 d;asm("fma.rn.f32x2 %0,%1,%2,%3;":"=l"(d):"l"(a),"l"(b),"l"(c));return d;}
__device__ __forceinline__ u64 add2(u64 a,u64 b){u64 d;asm("add.rn.f32x2 %0,%1,%2;":"=l"(d):"l"(a),"l"(b));return d;}
__device__ __forceinline__ u64 mul2(u64 a,u64 b){u64 d;asm("mul.rn.f32x2 %0,%1,%2;":"=l"(d):"l"(a),"l"(b));return d;}

// ---------------------------------------------------------------------------
// prep1: Wc = W_su @ W_out; build paired weight tables
// ---------------------------------------------------------------------------
__global__ void prep1(const float* __restrict__ W_su, const float* __restrict__ W_out,
                      const float* __restrict__ ln_g){
    int t = blockIdx.x*blockDim.x + threadIdx.x;
    if (t >= WSZ) return;
    int c = t / NPAIR, ap = t - c*NPAIR;
    int a0 = 2*ap, a1 = 2*ap+1;
    const float* wr = W_su + (size_t)c*CFRAME;
    float wc0 = 0.f, wc1 = 0.f;
    for (int s = 0; s < CFRAME; s++){
        float v = wr[s];
        wc0 = fmaf(v, W_out[s*NAA+a0], wc0);
        if (a1 < NAA) wc1 = fmaf(v, W_out[s*NAA+a1], wc1);
    }
    g_Wc[c*NAA+a0] = wc0;
    if (a1 < NAA) g_Wc[c*NAA+a1] = wc1;
    float g = ln_g[c];
    g_Wg2[t] = make_float2(g*wc0, (ap==NPAIR-1) ? 1.0f : g*wc1);   // ones column in pair10.y
    g_Wo2[t] = make_float2(W_out[c*NAA+a0], (a1<NAA) ? W_out[c*NAA+a1] : 0.f);
}

// ---------------------------------------------------------------------------
// prep2: A, B vectors (needs g_Wc from prep1)
// ---------------------------------------------------------------------------
__global__ void prep2(const float* __restrict__ ln_g, const float* __restrict__ ln_b,
                      const float* __restrict__ b_su, const float* __restrict__ W_out,
                      const float* __restrict__ b_out){
    __shared__ float As[NAA], Bs[NAA];
    int t = threadIdx.x;
    if (t < NAA){
        float A = 0.f, Bv = 0.f;
        for (int c = 0; c < CFRAME; c++){
            float wc = g_Wc[c*NAA+t];
            A  = fmaf(ln_g[c], wc, A);
            Bv = fmaf(ln_b[c], wc, Bv);
        }
        for (int s = 0; s < CFRAME; s++)
            Bv = fmaf(b_su[s], W_out[s*NAA+t], Bv);
        As[t] = A; Bs[t] = Bv;
    }
    __syncthreads();
    if (t < NPAIR){
        int a0 = 2*t, a1 = 2*t+1;
        g_A2[t]  = make_float2(As[a0], a1<NAA ? As[a1] : 0.f);
        g_B2[t]  = make_float2(Bs[a0], a1<NAA ? Bs[a1] : 0.f);
        g_Bo2[t] = make_float2(b_out[a0], a1<NAA ? b_out[a1] : 0.f);
    }
}

// index dtype probe (JAX int64 may canonicalize to int32)
__global__ void detect_idx_kernel(const void* __restrict__ idx_ptr){
    if (threadIdx.x == 0 && blockIdx.x == 0){
        const long long* p = (const long long*)idx_ptr;
        int is64 = 1;
        for (int i = 0; i < 64; i++){
            long long v = p[i];
            if (v < 0 || v >= NRES){ is64 = 0; break; }
        }
        g_idx64 = is64;
    }
}

// ---------------------------------------------------------------------------
// res_proj: out[row,:] = seq_out[row,:] @ W_out + b_out   (initializes d_out)
// 4-row blocked, f32x2 pairs, warp-per-4-rows.
// ---------------------------------------------------------------------------
__global__ void __launch_bounds__(THREADS,2)
res_proj_kernel(const float* __restrict__ sx, float* __restrict__ out){
    extern __shared__ float2 sm[];
    for (int i = threadIdx.x; i < WSZ; i += THREADS) sm[i] = g_Wo2[i];
    __syncthreads();
    const u64* Wsh = (const u64*)sm;
    u64* stage = (u64*)(sm + WSZ);

    const int lane = threadIdx.x & 31;
    const int w    = threadIdx.x >> 5;
    u64* st = stage + w*32*STRIDE;
    const int p = (lane < NPAIR) ? lane : (lane < 22 ? lane - NPAIR : 0);
    const u64 B2v = ((const u64*)g_Bo2)[p];
    const u64* wbase = Wsh + lane*NPAIR;

    const int totalWarps = gridDim.x * WARPS;
    const int ngroups = (BATCH*NRES)/4;
    for (int grp = blockIdx.x*WARPS + w; grp < ngroups; grp += totalWarps){
        const int row0 = grp*4;
        const float* xr = sx + (size_t)row0*CFRAME + lane;
        u64 acc[4][NPAIR];
        #pragma unroll
        for (int r = 0; r < 4; r++)
            #pragma unroll
            for (int q = 0; q < NPAIR; q++) acc[r][q] = 0ull;
        #pragma unroll
        for (int k = 0; k < KITER; k++){
            u64 xd[4];
            #pragma unroll
            for (int r = 0; r < 4; r++) xd[r] = dup2(xr[(size_t)r*CFRAME + 32*k]);
            const u64* wk = wbase + 32*k*NPAIR;
            #pragma unroll
            for (int q = 0; q < NPAIR; q++){
                u64 wv = wk[q];
                acc[0][q] = fma2(xd[0], wv, acc[0][q]);
                acc[1][q] = fma2(xd[1], wv, acc[1][q]);
                acc[2][q] = fma2(xd[2], wv, acc[2][q]);
                acc[3][q] = fma2(xd[3], wv, acc[3][q]);
            }
        }
        #pragma unroll
        for (int gp = 0; gp < 2; gp++){
            const int rA = 2*gp, rB = rA+1;
            #pragma unroll
            for (int q = 0; q < NPAIR; q++){
                st[lane*STRIDE + q]         = acc[rA][q];
                st[lane*STRIDE + NPAIR + q] = acc[rB][q];
            }
            __syncwarp();
            u64 sum = 0ull;
            if (lane < 22){
                u64 p0=0,p1=0,p2=0,p3=0;
                #pragma unroll
                for (int l = 0; l < 32; l += 4){
                    p0 = add2(p0, st[(l+0)*STRIDE + lane]);
                    p1 = add2(p1, st[(l+1)*STRIDE + lane]);
                    p2 = add2(p2, st[(l+2)*STRIDE + lane]);
                    p3 = add2(p3, st[(l+3)*STRIDE + lane]);
                }
                sum = add2(add2(p0,p1), add2(p2,p3));
            }
            __syncwarp();
            if (lane < 22){
                u64 outp = add2(sum, B2v);
                float o0, o1; upk2(outp, o0, o1);
                const int row = row0 + ((lane < NPAIR) ? rA : rB);
                float* dst = out + (size_t)row*NAA + 2*p;
                dst[0] = o0;
                if (2*p+1 < NAA) dst[1] = o1;
            }
            __syncwarp();
        }
    }
}

// ---------------------------------------------------------------------------
// rigid: LN folded into weights. Per row: dot over raw x with Wg (+ ones col
// giving s), s2 via FMA, then out[a] = rstd*(dot - mu*A) + B, *mask, scatter.
// ---------------------------------------------------------------------------
__global__ void __launch_bounds__(THREADS,2)
rigid_kernel(const float* __restrict__ x, const void* __restrict__ idxp,
             const float* __restrict__ mask, float* __restrict__ out){
    extern __shared__ float2 sm[];
    for (int i = threadIdx.x; i < WSZ; i += THREADS) sm[i] = g_Wg2[i];
    __syncthreads();
    const u64* Wsh = (const u64*)sm;
    u64* stage = (u64*)(sm + WSZ);

    const int lane = threadIdx.x & 31;
    const int w    = threadIdx.x >> 5;
    u64* st = stage + w*32*STRIDE;
    const long long* i64 = (const long long*)idxp;
    const int*       i32 = (const int*)idxp;
    const int use64 = g_idx64;
    const int p = (lane < NPAIR) ? lane : (lane < 22 ? lane - NPAIR : 0);
    const u64 A2v = ((const u64*)g_A2)[p];
    const u64 B2v = ((const u64*)g_B2)[p];
    const u64* wbase = Wsh + lane*NPAIR;

    const int totalWarps = gridDim.x * WARPS;
    const int ngroups = (BATCH*NRIG)/4;
    for (int grp = blockIdx.x*WARPS + w; grp < ngroups; grp += totalWarps){
        const int row0 = grp*4;
        const float* xr = x + (size_t)row0*CFRAME + lane;
        u64 acc[4][NPAIR];
        #pragma unroll
        for (int r = 0; r < 4; r++)
            #pragma unroll
            for (int q = 0; q < NPAIR; q++) acc[r][q] = 0ull;
        float s2[4] = {0.f,0.f,0.f,0.f};
        #pragma unroll
        for (int k = 0; k < KITER; k++){
            float xv[4]; u64 xd[4];
            #pragma unroll
            for (int r = 0; r < 4; r++) xv[r] = xr[(size_t)r*CFRAME + 32*k];
            #pragma unroll
            for (int r = 0; r < 4; r++){ s2[r] = fmaf(xv[r], xv[r], s2[r]); xd[r] = dup2(xv[r]); }
            const u64* wk = wbase + 32*k*NPAIR;
            #pragma unroll
            for (int q = 0; q < NPAIR; q++){
                u64 wv = wk[q];
                acc[0][q] = fma2(xd[0], wv, acc[0][q]);
                acc[1][q] = fma2(xd[1], wv, acc[1][q]);
                acc[2][q] = fma2(xd[2], wv, acc[2][q]);
                acc[3][q] = fma2(xd[3], wv, acc[3][q]);
            }
        }
        int ridx[4]; float msk[4];
        #pragma unroll
        for (int r = 0; r < 4; r++){
            ridx[r] = use64 ? (int)i64[row0+r] : i32[row0+r];
            msk[r]  = mask[row0+r];
        }
        float* outb = out + (size_t)(row0 >> 13)*NRES*NAA;   // batch base (NRIG=8192)

        #pragma unroll
        for (int gp = 0; gp < 2; gp++){
            const int rA = 2*gp, rB = rA+1;
            #pragma unroll
            for (int q = 0; q < NPAIR; q++){
                st[lane*STRIDE + q]         = acc[rA][q];
                st[lane*STRIDE + NPAIR + q] = acc[rB][q];
            }
            st[lane*STRIDE + 22] = pk2(s2[rA], s2[rB]);
            __syncwarp();
            u64 sum = 0ull;
            if (lane < 23){
                u64 p0=0,p1=0,p2=0,p3=0;
                #pragma unroll
                for (int l = 0; l < 32; l += 4){
                    p0 = add2(p0, st[(l+0)*STRIDE + lane]);
                    p1 = add2(p1, st[(l+1)*STRIDE + lane]);
                    p2 = add2(p2, st[(l+2)*STRIDE + lane]);
                    p3 = add2(p3, st[(l+3)*STRIDE + lane]);
                }
                sum = add2(add2(p0,p1), add2(p2,p3));
            }
            __syncwarp();
            float slo, shi; upk2(sum, slo, shi);
            const float sA  = __shfl_sync(0xffffffffu, shi, 10);  // pair10.y of row A = sum(x)
            const float sB  = __shfl_sync(0xffffffffu, shi, 21);
            const float s2A = __shfl_sync(0xffffffffu, slo, 22);
            const float s2B = __shfl_sync(0xffffffffu, shi, 22);
            const float muA = sA*(1.f/CFRAME), muB = sB*(1.f/CFRAME);
            const float rsA = rsqrtf(fmaf(s2A, 1.f/CFRAME, -muA*muA) + 1e-5f);
            const float rsB = rsqrtf(fmaf(s2B, 1.f/CFRAME, -muB*muB) + 1e-5f);
            if (lane < 22){
                const bool first = (lane < NPAIR);
                const float mu = first ? muA : muB;
                const float rs = first ? rsA : rsB;
                const float m  = first ? msk[rA] : msk[rB];
                const int   iv = first ? ridx[rA] : ridx[rB];
                u64 t1   = fma2(dup2(-mu), A2v, sum);                    // dot - mu*A
                u64 outp = fma2(dup2(rs*m), t1, mul2(dup2(m), B2v));     // m*(rstd*... + B)
                float o0, o1; upk2(outp, o0, o1);
                if (m != 0.f){
                    float* dst = outb + (size_t)iv*NAA + 2*p;
                    atomicAdd(dst, o0);
                    if (2*p+1 < NAA) atomicAdd(dst+1, o1);
                }
            }
            __syncwarp();
        }
    }
}

// ---------------------------------------------------------------------------
extern "C" void kernel_launch(void* const* d_in, const int* in_sizes, int n_in,
                              void* d_out, int out_size) {
    const float* x     = (const float*)d_in[0];  // rigids_embed_flat [16,8192,384]
    const void*  idxp  = d_in[1];                // rigids_to_res_idx [16,8192]
    const float* mask  = (const float*)d_in[2];  // rigids_mask [16,8192]
    const float* seqo  = (const float*)d_in[3];  // out [16,2048,384]
    const float* ln_g  = (const float*)d_in[4];
    const float* ln_b  = (const float*)d_in[5];
    const float* W_su  = (const float*)d_in[6];  // [384,384]
    const float* b_su  = (const float*)d_in[7];  // [384]
    const float* W_out = (const float*)d_in[8];  // [384,21]
    const float* b_out = (const float*)d_in[9];  // [21]
    float* out = (float*)d_out;                  // [16,2048,21]

    cudaFuncSetAttribute(res_proj_kernel,
                         cudaFuncAttributeMaxDynamicSharedMemorySize, SMEM_BYTES);
    cudaFuncSetAttribute(rigid_kernel,
                         cudaFuncAttributeMaxDynamicSharedMemorySize, SMEM_BYTES);

    prep1<<<(WSZ + 255)/256, 256>>>(W_su, W_out, ln_g);
    prep2<<<1, 64>>>(ln_g, ln_b, b_su, W_out, b_out);
    detect_idx_kernel<<<1, 32>>>(idxp);
    res_proj_kernel<<<NBLOCKS, THREADS, SMEM_BYTES>>>(seqo, out);
    rigid_kernel<<<NBLOCKS, THREADS, SMEM_BYTES>>>(x, idxp, mask, out);
}

// round 3
// speedup vs baseline: 1.3270x; 1.0400x over previous
#include <cuda_runtime.h>

#define CFRAME 384
#define NAA    21
#define NPAIR  11          // a-pairs; pair10 = (a20, ones-column)
#define NRES   2048
#define NRIG   8192
#define BATCH  16
#define WARPS  8
#define THREADS 256
#define NBLOCKS 296        // 2 persistent blocks / SM
#define RIGID_BLOCKS 237
#define RES_BLOCKS (NBLOCKS - RIGID_BLOCKS)
#define STRIDE 25          // stage stride in float2 (odd -> conflict-free)
#define WSZ (CFRAME*NPAIR)           // weight float2 count
#define STAGESZ (WARPS*32*STRIDE)    // stage float2 count
#define SMEM_BYTES ((WSZ+STAGESZ)*8)
#define NG_RIGID ((BATCH*NRIG)/4)    // 32768 groups of 4 rows
#define NG_RES   ((BATCH*NRES)/4)    // 8192 groups

typedef unsigned long long u64;

// device scratch (no allocations allowed)
__device__ float2 g_Wg2[WSZ];   // ln_g-folded Wc, permuted slots; pair10.y = 1 (ones col)
__device__ float2 g_Wo2[WSZ];   // W_out, permuted slots; pair10.y = 0
__device__ float2 g_A2[NPAIR];  // A = sum_c g*Wc
__device__ float2 g_B2[NPAIR];  // B = sum_c b*Wc + b_su@W_out
__device__ float2 g_Bo2[NPAIR]; // b_out pairs
__device__ float  g_Wc[CFRAME*NAA];
__device__ int    g_idx64;

// ---- packed f32x2 helpers ----
__device__ __forceinline__ u64 pk2(float lo, float hi){u64 r;asm("mov.b64 %0,{%1,%2};":"=l"(r):"f"(lo),"f"(hi));return r;}
__device__ __forceinline__ u64 dup2(float v){return pk2(v,v);}
__device__ __forceinline__ void upk2(u64 v,float&lo,float&hi){asm("mov.b64 {%0,%1},%2;":"=f"(lo),"=f"(hi):"l"(v));}
__device__ __forceinline__ u64 fma2(u64 a,u64 b,u64 c){u64 d;asm("fma.rn.f32x2 %0,%1,%2,%3;":"=l"(d):"l"(a),"l"(b),"l"(c));return d;}
__device__ __forceinline__ u64 add2(u64 a,u64 b){u64 d;asm("add.rn.f32x2 %0,%1,%2;":"=l"(d):"l"(a),"l"(b));return d;}
__device__ __forceinline__ u64 mul2(u64 a,u64 b){u64 d;asm("mul.rn.f32x2 %0,%1,%2;":"=l"(d):"l"(a),"l"(b));return d;}

// ---------------------------------------------------------------------------
// prep1: Wc = W_su @ W_out; build paired, slot-permuted weight tables.
// channel c = 4*L + i + 128*j  ->  slot = i*96 + j*32 + L  (L = lane)
// ---------------------------------------------------------------------------
__global__ void prep1(const float* __restrict__ W_su, const float* __restrict__ W_out,
                      const float* __restrict__ ln_g){
    int t = blockIdx.x*blockDim.x + threadIdx.x;
    if (t >= WSZ) return;
    int c = t / NPAIR, ap = t - c*NPAIR;
    int a0 = 2*ap, a1 = 2*ap+1;
    const float* wr = W_su + (size_t)c*CFRAME;
    float wc0 = 0.f, wc1 = 0.f;
    for (int s = 0; s < CFRAME; s++){
        float v = wr[s];
        wc0 = fmaf(v, W_out[s*NAA+a0], wc0);
        if (a1 < NAA) wc1 = fmaf(v, W_out[s*NAA+a1], wc1);
    }
    g_Wc[c*NAA+a0] = wc0;
    if (a1 < NAA) g_Wc[c*NAA+a1] = wc1;
    int i = c & 3, t2 = c >> 2;
    int slot = i*96 + (t2 >> 5)*32 + (t2 & 31);
    float g = ln_g[c];
    g_Wg2[slot*NPAIR+ap] = make_float2(g*wc0, (ap==NPAIR-1) ? 1.0f : g*wc1);
    g_Wo2[slot*NPAIR+ap] = make_float2(W_out[c*NAA+a0], (a1<NAA) ? W_out[c*NAA+a1] : 0.f);
}

// ---------------------------------------------------------------------------
// prep2: A, B vectors (needs g_Wc from prep1)
// ---------------------------------------------------------------------------
__global__ void prep2(const float* __restrict__ ln_g, const float* __restrict__ ln_b,
                      const float* __restrict__ b_su, const float* __restrict__ W_out,
                      const float* __restrict__ b_out){
    __shared__ float As[NAA], Bs[NAA];
    int t = threadIdx.x;
    if (t < NAA){
        float A = 0.f, Bv = 0.f;
        for (int c = 0; c < CFRAME; c++){
            float wc = g_Wc[c*NAA+t];
            A  = fmaf(ln_g[c], wc, A);
            Bv = fmaf(ln_b[c], wc, Bv);
        }
        for (int s = 0; s < CFRAME; s++)
            Bv = fmaf(b_su[s], W_out[s*NAA+t], Bv);
        As[t] = A; Bs[t] = Bv;
    }
    __syncthreads();
    if (t < NPAIR){
        int a0 = 2*t, a1 = 2*t+1;
        g_A2[t]  = make_float2(As[a0], a1<NAA ? As[a1] : 0.f);
        g_B2[t]  = make_float2(Bs[a0], a1<NAA ? Bs[a1] : 0.f);
        g_Bo2[t] = make_float2(b_out[a0], a1<NAA ? b_out[a1] : 0.f);
    }
}

// index dtype probe (JAX int64 may canonicalize to int32)
__global__ void detect_idx_kernel(const void* __restrict__ idx_ptr){
    if (threadIdx.x == 0 && blockIdx.x == 0){
        const long long* p = (const long long*)idx_ptr;
        int is64 = 1;
        for (int i = 0; i < 64; i++){
            long long v = p[i];
            if (v < 0 || v >= NRES){ is64 = 0; break; }
        }
        g_idx64 = is64;
    }
}

// one j-phase (128 channels) of the 4-row blocked dot products
__device__ __forceinline__ void comp_j(u64 acc[4][NPAIR], float s2[4],
                                       const u64* __restrict__ Wsh,
                                       int lane, int j, const float4 xq[4]){
    const float* xf = (const float*)xq;
    #pragma unroll
    for (int i = 0; i < 4; i++){
        const u64* wk = Wsh + (unsigned)(i*96 + j*32 + lane)*NPAIR;
        u64 xd[4];
        #pragma unroll
        for (int r = 0; r < 4; r++){
            float xv = xf[r*4 + i];
            s2[r] = fmaf(xv, xv, s2[r]);
            xd[r] = dup2(xv);
        }
        #pragma unroll
        for (int q = 0; q < NPAIR; q++){
            u64 wv = wk[q];
            acc[0][q] = fma2(xd[0], wv, acc[0][q]);
            acc[1][q] = fma2(xd[1], wv, acc[1][q]);
            acc[2][q] = fma2(xd[2], wv, acc[2][q]);
            acc[3][q] = fma2(xd[3], wv, acc[3][q]);
        }
    }
}

// ---------------------------------------------------------------------------
// fused kernel: blocks [0, RIGID_BLOCKS) process rigid 4-row groups
// (LN folded into weights, scatter atomics); blocks [RIGID_BLOCKS, NBLOCKS)
// process residue 4-row groups (out @ W_out + b_out, atomicAdd on zeroed out).
// ---------------------------------------------------------------------------
__global__ void __launch_bounds__(THREADS,2)
fused_kernel(const float* __restrict__ x, const void* __restrict__ idxp,
             const float* __restrict__ mask, const float* __restrict__ seqo,
             float* __restrict__ out){
    extern __shared__ float2 sm[];
    const bool isRes = (blockIdx.x >= RIGID_BLOCKS);
    {
        const float2* wsrc = isRes ? g_Wo2 : g_Wg2;
        for (int i = threadIdx.x; i < WSZ; i += THREADS) sm[i] = wsrc[i];
    }
    __syncthreads();
    const u64* Wsh = (const u64*)sm;
    u64* stage = (u64*)(sm + WSZ);

    const int lane = threadIdx.x & 31;
    const int w    = threadIdx.x >> 5;
    u64* st = stage + w*32*STRIDE;

    const long long* i64 = (const long long*)idxp;
    const int*       i32 = (const int*)idxp;
    const int use64 = g_idx64;
    const int p = (lane < NPAIR) ? lane : (lane < 22 ? lane - NPAIR : 0);
    const u64 A2v = ((const u64*)g_A2)[p];
    const u64 B2v = isRes ? ((const u64*)g_Bo2)[p] : ((const u64*)g_B2)[p];

    const int pb        = isRes ? (blockIdx.x - RIGID_BLOCKS) : blockIdx.x;
    const int strideW   = (isRes ? RES_BLOCKS : RIGID_BLOCKS) * WARPS;
    const int ngroups   = isRes ? NG_RES : NG_RIGID;
    const float* xbase  = isRes ? seqo : x;

    for (int grp = pb*WARPS + w; grp < ngroups; grp += strideW){
        const int row0 = grp*4;
        const float* xr = xbase + (size_t)row0*CFRAME + 4*lane;

        float4 xa[4], xb[4];
        #pragma unroll
        for (int r = 0; r < 4; r++) xa[r] = *(const float4*)(xr + r*CFRAME);
        #pragma unroll
        for (int r = 0; r < 4; r++) xb[r] = *(const float4*)(xr + r*CFRAME + 128);

        int ridx[4]; float msk[4];
        if (!isRes){
            #pragma unroll
            for (int r = 0; r < 4; r++){
                ridx[r] = use64 ? (int)i64[row0+r] : i32[row0+r];
                msk[r]  = mask[row0+r];
            }
        }

        u64 acc[4][NPAIR];
        #pragma unroll
        for (int r = 0; r < 4; r++)
            #pragma unroll
            for (int q = 0; q < NPAIR; q++) acc[r][q] = 0ull;
        float s2[4] = {0.f,0.f,0.f,0.f};

        comp_j(acc, s2, Wsh, lane, 0, xa);
        #pragma unroll
        for (int r = 0; r < 4; r++) xa[r] = *(const float4*)(xr + r*CFRAME + 256);
        comp_j(acc, s2, Wsh, lane, 1, xb);
        comp_j(acc, s2, Wsh, lane, 2, xa);

        float* outb = out + (size_t)(isRes ? (row0 >> 11) : (row0 >> 13))*NRES*NAA;

        #pragma unroll
        for (int gp = 0; gp < 2; gp++){
            const int rA = 2*gp, rB = rA+1;
            #pragma unroll
            for (int q = 0; q < NPAIR; q++){
                st[lane*STRIDE + q]         = acc[rA][q];
                st[lane*STRIDE + NPAIR + q] = acc[rB][q];
            }
            st[lane*STRIDE + 22] = pk2(s2[rA], s2[rB]);
            __syncwarp();
            u64 sum = 0ull;
            if (lane < 23){
                u64 p0=0,p1=0,p2=0,p3=0;
                #pragma unroll
                for (int l = 0; l < 32; l += 4){
                    p0 = add2(p0, st[(l+0)*STRIDE + lane]);
                    p1 = add2(p1, st[(l+1)*STRIDE + lane]);
                    p2 = add2(p2, st[(l+2)*STRIDE + lane]);
                    p3 = add2(p3, st[(l+3)*STRIDE + lane]);
                }
                sum = add2(add2(p0,p1), add2(p2,p3));
            }
            __syncwarp();
            if (isRes){
                if (lane < 22){
                    u64 outp = add2(sum, B2v);
                    float o0, o1; upk2(outp, o0, o1);
                    const int row = row0 + ((lane < NPAIR) ? rA : rB);
                    float* dst = out + (size_t)row*NAA + 2*p;
                    atomicAdd(dst, o0);
                    if (2*p+1 < NAA) atomicAdd(dst+1, o1);
                }
            } else {
                float slo, shi; upk2(sum, slo, shi);
                const float sA  = __shfl_sync(0xffffffffu, shi, 10);  // ones col row A
                const float sB  = __shfl_sync(0xffffffffu, shi, 21);
                const float s2A = __shfl_sync(0xffffffffu, slo, 22);
                const float s2B = __shfl_sync(0xffffffffu, shi, 22);
                const float muA = sA*(1.f/CFRAME), muB = sB*(1.f/CFRAME);
                const float rsA = rsqrtf(fmaf(s2A, 1.f/CFRAME, -muA*muA) + 1e-5f);
                const float rsB = rsqrtf(fmaf(s2B, 1.f/CFRAME, -muB*muB) + 1e-5f);
                if (lane < 22){
                    const bool first = (lane < NPAIR);
                    const float mu = first ? muA : muB;
                    const float rs = first ? rsA : rsB;
                    const float m  = first ? msk[rA] : msk[rB];
                    const int   iv = first ? ridx[rA] : ridx[rB];
                    u64 t1   = fma2(dup2(-mu), A2v, sum);                 // dot - mu*A
                    u64 outp = fma2(dup2(rs*m), t1, mul2(dup2(m), B2v));  // m*(rstd*.. + B)
                    float o0, o1; upk2(outp, o0, o1);
                    if (m != 0.f){
                        float* dst = outb + (size_t)iv*NAA + 2*p;
                        atomicAdd(dst, o0);
                        if (2*p+1 < NAA) atomicAdd(dst+1, o1);
                    }
                }
            }
            __syncwarp();
        }
    }
}

// ---------------------------------------------------------------------------
extern "C" void kernel_launch(void* const* d_in, const int* in_sizes, int n_in,
                              void* d_out, int out_size) {
    const float* x     = (const float*)d_in[0];  // rigids_embed_flat [16,8192,384]
    const void*  idxp  = d_in[1];                // rigids_to_res_idx [16,8192]
    const float* mask  = (const float*)d_in[2];  // rigids_mask [16,8192]
    const float* seqo  = (const float*)d_in[3];  // out [16,2048,384]
    const float* ln_g  = (const float*)d_in[4];
    const float* ln_b  = (const float*)d_in[5];
    const float* W_su  = (const float*)d_in[6];  // [384,384]
    const float* b_su  = (const float*)d_in[7];  // [384]
    const float* W_out = (const float*)d_in[8];  // [384,21]
    const float* b_out = (const float*)d_in[9];  // [21]
    float* out = (float*)d_out;                  // [16,2048,21]

    cudaFuncSetAttribute(fused_kernel,
                         cudaFuncAttributeMaxDynamicSharedMemorySize, SMEM_BYTES);

    prep1<<<(WSZ + 255)/256, 256>>>(W_su, W_out, ln_g);
    prep2<<<1, 64>>>(ln_g, ln_b, b_su, W_out, b_out);
    detect_idx_kernel<<<1, 32>>>(idxp);
    cudaMemsetAsync(out, 0, (size_t)out_size * sizeof(float));
    fused_kernel<<<NBLOCKS, THREADS, SMEM_BYTES>>>(x, idxp, mask, seqo, out);
}

// round 5
// speedup vs baseline: 1.3849x; 1.0437x over previous
#include <cuda_runtime.h>

#define CFRAME 384
#define NAA    21
#define NRES   2048
#define NRIG   8192
#define BATCH  16
#define THREADS 256
#define NBLOCKS 296                     // exactly 2 blocks/SM (smem-capped)
#define WARPS_TOTAL (NBLOCKS*8)         // 2368
#define RIGID_TILES ((BATCH*NRIG)/32)   // 4096
#define RES_TILES   ((BATCH*NRES)/32)   // 1024
#define NTILES (RIGID_TILES + RES_TILES)// 5120
#define WTAB   (CFRAME*6)               // float4 per weight table (2304)
#define CH9    9                        // stage row stride in float4 (8 used + 1 pad)
#define STAGE_F4 (32*CH9)               // 288 float4 per warp
#define SMEM_F4 (2*WTAB + 8*STAGE_F4)   // 6912 float4
#define SMEM_BYTES (SMEM_F4*16)         // 110592

typedef unsigned long long u64;

// ---------------- device scratch (no allocations) ---------------------------
__device__ float4 g_Wg[WTAB];    // rigid: g-folded Wc; [c*6+5] = (g*wc20, 1, 0, 0)
__device__ float4 g_Wo[WTAB];    // res:   W_out;       [c*6+5] = (w20, 0, 0, 0)
__device__ float2 g_A2[11];      // A = sum_c g*Wc   (element 10 = (A20, 0))
__device__ float2 g_B2[11];      // B = sum_c b*Wc + b_su@W_out
__device__ float2 g_Bo2[11];     // b_out
__device__ float  g_Wc[CFRAME*NAA];
__device__ int    g_idx64;

// ---- packed f32x2 helpers ----
__device__ __forceinline__ u64 pk2(float lo, float hi){u64 r;asm("mov.b64 %0,{%1,%2};":"=l"(r):"f"(lo),"f"(hi));return r;}
__device__ __forceinline__ u64 dup2(float v){return pk2(v,v);}
__device__ __forceinline__ void upk2(u64 v,float&lo,float&hi){asm("mov.b64 {%0,%1},%2;":"=f"(lo),"=f"(hi):"l"(v));}
__device__ __forceinline__ u64 fma2(u64 a,u64 b,u64 c){u64 d;asm("fma.rn.f32x2 %0,%1,%2,%3;":"=l"(d):"l"(a),"l"(b),"l"(c));return d;}
__device__ __forceinline__ u64 mul2(u64 a,u64 b){u64 d;asm("mul.rn.f32x2 %0,%1,%2;":"=l"(d):"l"(a),"l"(b));return d;}

// ---------------------------------------------------------------------------
// prep1: Wc[c][j] = sum_s W_su[c][s] * W_out[s][j]
// ---------------------------------------------------------------------------
__global__ void prep1(const float* __restrict__ W_su, const float* __restrict__ W_out){
    int t = blockIdx.x*blockDim.x + threadIdx.x;
    if (t >= CFRAME*NAA) return;
    int c = t / NAA, j = t - c*NAA;
    const float* wr = W_su + (size_t)c*CFRAME;
    float acc = 0.f;
    for (int s = 0; s < CFRAME; s++) acc = fmaf(wr[s], W_out[s*NAA+j], acc);
    g_Wc[t] = acc;
}

// ---------------------------------------------------------------------------
// prep2: build both weight tables (device globals only) + epilogue vectors
// ---------------------------------------------------------------------------
__global__ void prep2(const float* __restrict__ ln_g, const float* __restrict__ ln_b,
                      const float* __restrict__ b_su, const float* __restrict__ W_out,
                      const float* __restrict__ b_out){
    int t = blockIdx.x*blockDim.x + threadIdx.x;
    if (t < CFRAME){
        int c = t;
        float g = ln_g[c];
        const float* wc = g_Wc + c*NAA;
        const float* wo = W_out + c*NAA;
        #pragma unroll
        for (int k = 0; k < 5; k++){
            g_Wg[c*6+k] = make_float4(g*wc[4*k], g*wc[4*k+1], g*wc[4*k+2], g*wc[4*k+3]);
            g_Wo[c*6+k] = make_float4(wo[4*k], wo[4*k+1], wo[4*k+2], wo[4*k+3]);
        }
        g_Wg[c*6+5] = make_float4(g*wc[20], 1.0f, 0.f, 0.f);   // ones col -> sum(x)
        g_Wo[c*6+5] = make_float4(wo[20],   0.0f, 0.f, 0.f);
    } else if (t < CFRAME + NAA){
        int j = t - CFRAME;
        float A = 0.f, Bv = 0.f;
        for (int c = 0; c < CFRAME; c++){
            float wc = g_Wc[c*NAA+j];
            A  = fmaf(ln_g[c], wc, A);
            Bv = fmaf(ln_b[c], wc, Bv);
        }
        for (int s = 0; s < CFRAME; s++)
            Bv = fmaf(b_su[s], W_out[s*NAA+j], Bv);
        ((float*)g_A2)[j]  = A;
        ((float*)g_B2)[j]  = Bv;
        ((float*)g_Bo2)[j] = b_out[j];
        if (j == 20){ ((float*)g_A2)[21]=0.f; ((float*)g_B2)[21]=0.f; ((float*)g_Bo2)[21]=0.f; }
    }
}

// index dtype probe (JAX int64 may canonicalize to int32)
__global__ void detect_idx_kernel(const void* __restrict__ idx_ptr){
    if (threadIdx.x == 0 && blockIdx.x == 0){
        const long long* p = (const long long*)idx_ptr;
        int is64 = 1;
        for (int i = 0; i < 64; i++){
            long long v = p[i];
            if (v < 0 || v >= NRES){ is64 = 0; break; }
        }
        g_idx64 = is64;
    }
}

// ---------------------------------------------------------------------------
// tile engine: lane owns one row of a 32-row tile. Full 384-dot in-lane.
// Weights read from SMEM with warp-uniform addresses (broadcast, no conflicts).
// acc[10] = (accS, sum(x)) via the ones column.
// ---------------------------------------------------------------------------
template<bool RES>
__device__ __forceinline__ void do_tile(int row0, const float* __restrict__ xbase,
                                        const float4* __restrict__ W,
                                        const void* __restrict__ idxp,
                                        const float* __restrict__ mask,
                                        float* __restrict__ out,
                                        float4* __restrict__ xs, int lane, int use64){
    u64 acc[11];
    #pragma unroll
    for (int q = 0; q < 11; q++) acc[q] = 0ull;
    float s2 = 0.f;

    const int qld = lane & 7, sub = lane >> 3;

    for (int cb = 0; cb < 12; cb++){
        #pragma unroll
        for (int r = 0; r < 8; r++){
            int row = r*4 + sub;
            xs[row*CH9 + qld] =
                *(const float4*)(xbase + (size_t)(row0+row)*CFRAME + cb*32 + qld*4);
        }
        __syncwarp();
        #pragma unroll 2
        for (int i = 0; i < 8; i++){
            float4 xv = xs[lane*CH9 + i];
            const float xf4[4] = {xv.x, xv.y, xv.z, xv.w};
            #pragma unroll
            for (int u = 0; u < 4; u++){
                const int c = cb*32 + i*4 + u;
                const float xf = xf4[u];
                if (!RES) s2 = fmaf(xf, xf, s2);
                const u64 xd = dup2(xf);
                const float4* wc = W + c*6;
                float4 w0 = wc[0], w1 = wc[1], w2 = wc[2], w3 = wc[3], w4 = wc[4];
                float2 w5 = *(const float2*)(wc + 5);
                acc[0] = fma2(xd, pk2(w0.x,w0.y), acc[0]);
                acc[1] = fma2(xd, pk2(w0.z,w0.w), acc[1]);
                acc[2] = fma2(xd, pk2(w1.x,w1.y), acc[2]);
                acc[3] = fma2(xd, pk2(w1.z,w1.w), acc[3]);
                acc[4] = fma2(xd, pk2(w2.x,w2.y), acc[4]);
                acc[5] = fma2(xd, pk2(w2.z,w2.w), acc[5]);
                acc[6] = fma2(xd, pk2(w3.x,w3.y), acc[6]);
                acc[7] = fma2(xd, pk2(w3.z,w3.w), acc[7]);
                acc[8] = fma2(xd, pk2(w4.x,w4.y), acc[8]);
                acc[9] = fma2(xd, pk2(w4.z,w4.w), acc[9]);
                acc[10]= fma2(xd, pk2(w5.x,w5.y), acc[10]);   // (accS, sum x)
            }
        }
        __syncwarp();
    }

    const int row = row0 + lane;
    if (RES){
        float* dst = out + (size_t)row*NAA;
        #pragma unroll
        for (int q = 0; q < 10; q++){
            float2 bo = g_Bo2[q];
            float o0, o1; upk2(acc[q], o0, o1);
            atomicAdd(dst + 2*q,     o0 + bo.x);
            atomicAdd(dst + 2*q + 1, o1 + bo.y);
        }
        float accS, dumm; upk2(acc[10], accS, dumm);
        atomicAdd(dst + 20, accS + g_Bo2[10].x);
    } else {
        float accS, s; upk2(acc[10], accS, s);
        const float mu = s * (1.f/CFRAME);
        const float rs = rsqrtf(fmaf(s2, 1.f/CFRAME, -mu*mu) + 1e-5f);
        const float m  = mask[row];
        const int iv = use64 ? (int)((const long long*)idxp)[row]
                             : ((const int*)idxp)[row];
        if (m != 0.f){
            float* dst = out + ((size_t)(row >> 13)*NRES + (size_t)iv)*NAA;
            const float rm = rs*m;
            const u64 rmd = dup2(rm), md = dup2(m), nmud = dup2(-mu);
            #pragma unroll
            for (int q = 0; q < 10; q++){
                float2 a = g_A2[q], b = g_B2[q];
                u64 o = fma2(nmud, pk2(a.x,a.y), acc[q]);      // acc - mu*A
                o     = fma2(rmd, o, mul2(md, pk2(b.x,b.y)));  // rs*m*(..) + m*B
                float o0, o1; upk2(o, o0, o1);
                atomicAdd(dst + 2*q,     o0);
                atomicAdd(dst + 2*q + 1, o1);
            }
            float oS = rm*(accS - mu*g_A2[10].x) + m*g_B2[10].x;
            atomicAdd(dst + 20, oS);
        }
    }
}

// ---------------------------------------------------------------------------
// fused kernel: unified tile space; both weight tables resident in SMEM.
// tiles [0,4096) rigid, [4096,5120) res. Grid-stride over tiles.
// ---------------------------------------------------------------------------
__global__ void __launch_bounds__(THREADS,2)
fused_kernel(const float* __restrict__ x, const void* __restrict__ idxp,
             const float* __restrict__ mask, const float* __restrict__ seqo,
             float* __restrict__ out){
    extern __shared__ float4 sm4[];
    float4* Wg = sm4;                 // WTAB
    float4* Wo = sm4 + WTAB;          // WTAB
    const int lane = threadIdx.x & 31;
    const int w    = threadIdx.x >> 5;
    float4* xs = sm4 + 2*WTAB + w*STAGE_F4;

    for (int i = threadIdx.x; i < WTAB; i += THREADS){
        Wg[i] = g_Wg[i];
        Wo[i] = g_Wo[i];
    }
    __syncthreads();
    const int use64 = g_idx64;

    const int gw = blockIdx.x*8 + w;
    for (int t = gw; t < NTILES; t += WARPS_TOTAL){
        if (t < RIGID_TILES)
            do_tile<false>(t*32, x, Wg, idxp, mask, out, xs, lane, use64);
        else
            do_tile<true>((t-RIGID_TILES)*32, seqo, Wo, idxp, mask, out, xs, lane, use64);
    }
}

// ---------------------------------------------------------------------------
extern "C" void kernel_launch(void* const* d_in, const int* in_sizes, int n_in,
                              void* d_out, int out_size) {
    const float* x     = (const float*)d_in[0];  // rigids_embed_flat [16,8192,384]
    const void*  idxp  = d_in[1];                // rigids_to_res_idx [16,8192]
    const float* mask  = (const float*)d_in[2];  // rigids_mask [16,8192]
    const float* seqo  = (const float*)d_in[3];  // out [16,2048,384]
    const float* ln_g  = (const float*)d_in[4];
    const float* ln_b  = (const float*)d_in[5];
    const float* W_su  = (const float*)d_in[6];  // [384,384]
    const float* b_su  = (const float*)d_in[7];  // [384]
    const float* W_out = (const float*)d_in[8];  // [384,21]
    const float* b_out = (const float*)d_in[9];  // [21]
    float* out = (float*)d_out;                  // [16,2048,21]

    cudaFuncSetAttribute(fused_kernel,
                         cudaFuncAttributeMaxDynamicSharedMemorySize, SMEM_BYTES);

    prep1<<<(CFRAME*NAA + 255)/256, 256>>>(W_su, W_out);
    prep2<<<2, 256>>>(ln_g, ln_b, b_su, W_out, b_out);
    detect_idx_kernel<<<1, 32>>>(idxp);
    cudaMemsetAsync(out, 0, (size_t)out_size * sizeof(float));
    fused_kernel<<<NBLOCKS, THREADS, SMEM_BYTES>>>(x, idxp, mask, seqo, out);
}

// round 6
// speedup vs baseline: 1.6150x; 1.1661x over previous
#include <cuda_runtime.h>

#define CFRAME 384
#define NAA    21
#define NRES   2048
#define NRIG   8192
#define BATCH  16
#define THREADS 128                     // 4 warps per block
#define NBLOCKS 296                     // 2 blocks/SM (smem-capped)
#define WARPS_TOTAL (NBLOCKS*4)         // 1184
#define TILE_ROWS 64
#define RIGID_TILES ((BATCH*NRIG)/TILE_ROWS)   // 2048
#define RES_TILES   ((BATCH*NRES)/TILE_ROWS)   // 512
#define NTILES (RIGID_TILES + RES_TILES)       // 2560
#define WTAB   (CFRAME*6)               // float4 per weight table (2304)
#define CH9    9                        // stage row stride in float4 (8 used + 1 pad)
#define STAGE_F4 (TILE_ROWS*CH9)        // 576 float4 per warp
#define SMEM_F4 (2*WTAB + 4*STAGE_F4)   // 6912 float4
#define SMEM_BYTES (SMEM_F4*16)         // 110592

typedef unsigned long long u64;

// ---------------- device scratch (no allocations) ---------------------------
__device__ float4 g_Wg[WTAB];    // rigid: g-folded Wc; [c*6+5] = (g*wc20, 1, 0, 0)
__device__ float4 g_Wo[WTAB];    // res:   W_out;       [c*6+5] = (w20, 0, 0, 0)
__device__ float2 g_A2[11];      // A = sum_c g*Wc   (element 10 = (A20, 0))
__device__ float2 g_B2[11];      // B = sum_c b*Wc + b_su@W_out
__device__ float2 g_Bo2[11];     // b_out
__device__ float  g_Wc[CFRAME*NAA];
__device__ int    g_idx64;

// ---- packed f32x2 helpers ----
__device__ __forceinline__ u64 pk2(float lo, float hi){u64 r;asm("mov.b64 %0,{%1,%2};":"=l"(r):"f"(lo),"f"(hi));return r;}
__device__ __forceinline__ u64 dup2(float v){return pk2(v,v);}
__device__ __forceinline__ void upk2(u64 v,float&lo,float&hi){asm("mov.b64 {%0,%1},%2;":"=f"(lo),"=f"(hi):"l"(v));}
__device__ __forceinline__ u64 fma2(u64 a,u64 b,u64 c){u64 d;asm("fma.rn.f32x2 %0,%1,%2,%3;":"=l"(d):"l"(a),"l"(b),"l"(c));return d;}
__device__ __forceinline__ u64 mul2(u64 a,u64 b){u64 d;asm("mul.rn.f32x2 %0,%1,%2;":"=l"(d):"l"(a),"l"(b));return d;}

// ---------------------------------------------------------------------------
// prep1: Wc[c][j] = sum_s W_su[c][s] * W_out[s][j]
// ---------------------------------------------------------------------------
__global__ void prep1(const float* __restrict__ W_su, const float* __restrict__ W_out){
    int t = blockIdx.x*blockDim.x + threadIdx.x;
    if (t >= CFRAME*NAA) return;
    int c = t / NAA, j = t - c*NAA;
    const float* wr = W_su + (size_t)c*CFRAME;
    float acc = 0.f;
    for (int s = 0; s < CFRAME; s++) acc = fmaf(wr[s], W_out[s*NAA+j], acc);
    g_Wc[t] = acc;
}

// ---------------------------------------------------------------------------
// prep2: build both weight tables + epilogue vectors + idx dtype probe
// ---------------------------------------------------------------------------
__global__ void prep2(const float* __restrict__ ln_g, const float* __restrict__ ln_b,
                      const float* __restrict__ b_su, const float* __restrict__ W_out,
                      const float* __restrict__ b_out, const void* __restrict__ idx_ptr){
    int t = blockIdx.x*blockDim.x + threadIdx.x;
    if (t < CFRAME){
        int c = t;
        float g = ln_g[c];
        const float* wc = g_Wc + c*NAA;
        const float* wo = W_out + c*NAA;
        #pragma unroll
        for (int k = 0; k < 5; k++){
            g_Wg[c*6+k] = make_float4(g*wc[4*k], g*wc[4*k+1], g*wc[4*k+2], g*wc[4*k+3]);
            g_Wo[c*6+k] = make_float4(wo[4*k], wo[4*k+1], wo[4*k+2], wo[4*k+3]);
        }
        g_Wg[c*6+5] = make_float4(g*wc[20], 1.0f, 0.f, 0.f);   // ones col -> sum(x)
        g_Wo[c*6+5] = make_float4(wo[20],   0.0f, 0.f, 0.f);
    } else if (t < CFRAME + NAA){
        int j = t - CFRAME;
        float A = 0.f, Bv = 0.f;
        for (int c = 0; c < CFRAME; c++){
            float wc = g_Wc[c*NAA+j];
            A  = fmaf(ln_g[c], wc, A);
            Bv = fmaf(ln_b[c], wc, Bv);
        }
        for (int s = 0; s < CFRAME; s++)
            Bv = fmaf(b_su[s], W_out[s*NAA+j], Bv);
        ((float*)g_A2)[j]  = A;
        ((float*)g_B2)[j]  = Bv;
        ((float*)g_Bo2)[j] = b_out[j];
        if (j == 20){ ((float*)g_A2)[21]=0.f; ((float*)g_B2)[21]=0.f; ((float*)g_Bo2)[21]=0.f; }
    } else if (t == CFRAME + NAA){
        const long long* p = (const long long*)idx_ptr;
        int is64 = 1;
        for (int i = 0; i < 64; i++){
            long long v = p[i];
            if (v < 0 || v >= NRES){ is64 = 0; break; }
        }
        g_idx64 = is64;
    }
}

// ---------------------------------------------------------------------------
// per-row epilogue helpers
// ---------------------------------------------------------------------------
__device__ __forceinline__ void epi_res(const u64 acc[11], float* __restrict__ out, int row){
    float* dst = out + (size_t)row*NAA;
    #pragma unroll
    for (int q = 0; q < 10; q++){
        float2 bo = g_Bo2[q];
        float o0, o1; upk2(acc[q], o0, o1);
        atomicAdd(dst + 2*q,     o0 + bo.x);
        atomicAdd(dst + 2*q + 1, o1 + bo.y);
    }
    float accS, dumm; upk2(acc[10], accS, dumm);
    atomicAdd(dst + 20, accS + g_Bo2[10].x);
}

__device__ __forceinline__ void epi_rigid(const u64 acc[11], float s2,
                                          const void* __restrict__ idxp,
                                          const float* __restrict__ mask,
                                          float* __restrict__ out, int row, int use64){
    float accS, s; upk2(acc[10], accS, s);
    const float mu = s * (1.f/CFRAME);
    const float rs = rsqrtf(fmaf(s2, 1.f/CFRAME, -mu*mu) + 1e-5f);
    const float m  = mask[row];
    const int iv = use64 ? (int)((const long long*)idxp)[row]
                         : ((const int*)idxp)[row];
    if (m != 0.f){
        float* dst = out + ((size_t)(row >> 13)*NRES + (size_t)iv)*NAA;
        const float rm = rs*m;
        const u64 rmd = dup2(rm), md = dup2(m), nmud = dup2(-mu);
        #pragma unroll
        for (int q = 0; q < 10; q++){
            float2 a = g_A2[q], b = g_B2[q];
            u64 o = fma2(nmud, pk2(a.x,a.y), acc[q]);      // acc - mu*A
            o     = fma2(rmd, o, mul2(md, pk2(b.x,b.y)));  // rs*m*(..) + m*B
            float o0, o1; upk2(o, o0, o1);
            atomicAdd(dst + 2*q,     o0);
            atomicAdd(dst + 2*q + 1, o1);
        }
        float oS = rm*(accS - mu*g_A2[10].x) + m*g_B2[10].x;
        atomicAdd(dst + 20, oS);
    }
}

// ---------------------------------------------------------------------------
// tile engine: 64-row tile, lane owns rows (lane, lane+32). Each weight load
// feeds both rows (2x amortization). Weights read warp-uniform from SMEM.
// acc[10] = (accS, sum x) via ones column.
// ---------------------------------------------------------------------------
template<bool RES>
__device__ __forceinline__ void do_tile(int row0, const float* __restrict__ xbase,
                                        const float4* __restrict__ W,
                                        const void* __restrict__ idxp,
                                        const float* __restrict__ mask,
                                        float* __restrict__ out,
                                        float4* __restrict__ xs, int lane, int use64){
    u64 accA[11], accB[11];
    #pragma unroll
    for (int q = 0; q < 11; q++){ accA[q] = 0ull; accB[q] = 0ull; }
    float s2A = 0.f, s2B = 0.f;

    const int qld = lane & 7, sub = lane >> 3;

    for (int cb = 0; cb < 12; cb++){
        // stage 64 rows x 32 channels (16 x LDG.128 per lane, coalesced)
        #pragma unroll
        for (int r = 0; r < 16; r++){
            int row = r*4 + sub;
            xs[row*CH9 + qld] =
                *(const float4*)(xbase + (size_t)(row0+row)*CFRAME + cb*32 + qld*4);
        }
        __syncwarp();
        #pragma unroll 2
        for (int i = 0; i < 8; i++){
            float4 xa = xs[lane*CH9 + i];              // row = lane
            float4 xb = xs[(lane+32)*CH9 + i];         // row = lane+32
            const float xf4a[4] = {xa.x, xa.y, xa.z, xa.w};
            const float xf4b[4] = {xb.x, xb.y, xb.z, xb.w};
            #pragma unroll
            for (int u = 0; u < 4; u++){
                const int c = cb*32 + i*4 + u;
                const float fa = xf4a[u], fb = xf4b[u];
                if (!RES){ s2A = fmaf(fa, fa, s2A); s2B = fmaf(fb, fb, s2B); }
                const u64 da = dup2(fa), db = dup2(fb);
                const float4* wc = W + c*6;
                float4 w0 = wc[0], w1 = wc[1], w2 = wc[2], w3 = wc[3], w4 = wc[4];
                float2 w5 = *(const float2*)(wc + 5);
                u64 p0 = pk2(w0.x,w0.y), p1 = pk2(w0.z,w0.w);
                u64 p2 = pk2(w1.x,w1.y), p3 = pk2(w1.z,w1.w);
                u64 p4 = pk2(w2.x,w2.y), p5 = pk2(w2.z,w2.w);
                u64 p6 = pk2(w3.x,w3.y), p7 = pk2(w3.z,w3.w);
                u64 p8 = pk2(w4.x,w4.y), p9 = pk2(w4.z,w4.w);
                u64 p10= pk2(w5.x,w5.y);
                accA[0] = fma2(da, p0, accA[0]);  accB[0] = fma2(db, p0, accB[0]);
                accA[1] = fma2(da, p1, accA[1]);  accB[1] = fma2(db, p1, accB[1]);
                accA[2] = fma2(da, p2, accA[2]);  accB[2] = fma2(db, p2, accB[2]);
                accA[3] = fma2(da, p3, accA[3]);  accB[3] = fma2(db, p3, accB[3]);
                accA[4] = fma2(da, p4, accA[4]);  accB[4] = fma2(db, p4, accB[4]);
                accA[5] = fma2(da, p5, accA[5]);  accB[5] = fma2(db, p5, accB[5]);
                accA[6] = fma2(da, p6, accA[6]);  accB[6] = fma2(db, p6, accB[6]);
                accA[7] = fma2(da, p7, accA[7]);  accB[7] = fma2(db, p7, accB[7]);
                accA[8] = fma2(da, p8, accA[8]);  accB[8] = fma2(db, p8, accB[8]);
                accA[9] = fma2(da, p9, accA[9]);  accB[9] = fma2(db, p9, accB[9]);
                accA[10]= fma2(da, p10, accA[10]);accB[10]= fma2(db, p10, accB[10]);
            }
        }
        __syncwarp();
    }

    if (RES){
        epi_res(accA, out, row0 + lane);
        epi_res(accB, out, row0 + lane + 32);
    } else {
        epi_rigid(accA, s2A, idxp, mask, out, row0 + lane,      use64);
        epi_rigid(accB, s2B, idxp, mask, out, row0 + lane + 32, use64);
    }
}

// ---------------------------------------------------------------------------
// fused kernel: unified tile space, grid-stride.
// tiles [0,2048) rigid (64 rows each), [2048,2560) res.
// ---------------------------------------------------------------------------
__global__ void __launch_bounds__(THREADS,2)
fused_kernel(const float* __restrict__ x, const void* __restrict__ idxp,
             const float* __restrict__ mask, const float* __restrict__ seqo,
             float* __restrict__ out){
    extern __shared__ float4 sm4[];
    float4* Wg = sm4;                 // WTAB
    float4* Wo = sm4 + WTAB;          // WTAB
    const int lane = threadIdx.x & 31;
    const int w    = threadIdx.x >> 5;
    float4* xs = sm4 + 2*WTAB + w*STAGE_F4;

    for (int i = threadIdx.x; i < WTAB; i += THREADS){
        Wg[i] = g_Wg[i];
        Wo[i] = g_Wo[i];
    }
    __syncthreads();
    const int use64 = g_idx64;

    const int gw = blockIdx.x*4 + w;
    for (int t = gw; t < NTILES; t += WARPS_TOTAL){
        if (t < RIGID_TILES)
            do_tile<false>(t*TILE_ROWS, x, Wg, idxp, mask, out, xs, lane, use64);
        else
            do_tile<true>((t-RIGID_TILES)*TILE_ROWS, seqo, Wo, idxp, mask, out, xs, lane, use64);
    }
}

// ---------------------------------------------------------------------------
extern "C" void kernel_launch(void* const* d_in, const int* in_sizes, int n_in,
                              void* d_out, int out_size) {
    const float* x     = (const float*)d_in[0];  // rigids_embed_flat [16,8192,384]
    const void*  idxp  = d_in[1];                // rigids_to_res_idx [16,8192]
    const float* mask  = (const float*)d_in[2];  // rigids_mask [16,8192]
    const float* seqo  = (const float*)d_in[3];  // out [16,2048,384]
    const float* ln_g  = (const float*)d_in[4];
    const float* ln_b  = (const float*)d_in[5];
    const float* W_su  = (const float*)d_in[6];  // [384,384]
    const float* b_su  = (const float*)d_in[7];  // [384]
    const float* W_out = (const float*)d_in[8];  // [384,21]
    const float* b_out = (const float*)d_in[9];  // [21]
    float* out = (float*)d_out;                  // [16,2048,21]

    cudaFuncSetAttribute(fused_kernel,
                         cudaFuncAttributeMaxDynamicSharedMemorySize, SMEM_BYTES);

    prep1<<<(CFRAME*NAA + 255)/256, 256>>>(W_su, W_out);
    prep2<<<2, 256>>>(ln_g, ln_b, b_su, W_out, b_out, idxp);
    cudaMemsetAsync(out, 0, (size_t)out_size * sizeof(float));
    fused_kernel<<<NBLOCKS, THREADS, SMEM_BYTES>>>(x, idxp, mask, seqo, out);
}